// round 2
// baseline (speedup 1.0000x reference)
#include <cuda_runtime.h>
#include <math.h>

// ---------------------------------------------------------------------------
// Problem constants
// ---------------------------------------------------------------------------
#define Nn   16
#define Cc   256
#define Hh   64
#define Ww   64
#define PH   66            // padded height (1 halo each side)
#define PW   72            // padded width (1+64+7; padded to mult of 8 for alignment)
#define NPIX (Cc*Hh*Ww)    // 1048576 elems per sample (GroupNorm group = whole sample)
#define PADTOT (Nn*Cc*PH*PW)   // 19,464,192
#define WTOT (Cc*Cc*9)         // 589,824
#define GN_EPSF 1e-5f

// ---------------------------------------------------------------------------
// Scratch (static __device__ globals -- no allocation in kernel_launch)
// ---------------------------------------------------------------------------
__device__ __align__(256) float g_xq[PADTOT];   // quantized activations, zero-padded halo
__device__ __align__(256) float g_wqT[WTOT];    // ternary weights {-1,0,1}, layout [tap][ic][oc]
__device__ double g_sum[Nn];
__device__ double g_sumsq[Nn];
__device__ double g_wabs;
__device__ unsigned int g_maxbits;
__device__ float g_meanf[Nn], g_istdf[Nn];
__device__ float g_qscale;   // 128 / gamma
__device__ float g_coef;     // 0.01 * gamma / 128
__device__ float g_delta;    // 0.7 * mean|w|

// ---------------------------------------------------------------------------
// K0: zero the reduction scratch (runs every launch -> graph-replay safe)
// ---------------------------------------------------------------------------
__global__ void k_init() {
    int t = threadIdx.x;
    if (t < Nn) { g_sum[t] = 0.0; g_sumsq[t] = 0.0; }
    if (t == 0) { g_wabs = 0.0; g_maxbits = 0u; }
}

// ---------------------------------------------------------------------------
// K1: per-sample sum / sumsq  (double-precision cross-block accumulation)
// grid (64, 16), 256 threads; each block covers 16384 contiguous elems
// ---------------------------------------------------------------------------
__global__ void k_stats(const float* __restrict__ x) {
    int n = blockIdx.y;
    const float* p = x + (size_t)n * NPIX + (size_t)blockIdx.x * 16384;
    int tid = threadIdx.x;
    float s = 0.f, ss = 0.f;
#pragma unroll
    for (int k = 0; k < 16; k++) {
        float4 v = *(const float4*)(p + tid * 4 + k * 1024);
        s  += v.x + v.y + v.z + v.w;
        ss += v.x*v.x + v.y*v.y + v.z*v.z + v.w*v.w;
    }
#pragma unroll
    for (int off = 16; off; off >>= 1) {
        s  += __shfl_xor_sync(0xffffffffu, s,  off);
        ss += __shfl_xor_sync(0xffffffffu, ss, off);
    }
    __shared__ double ws[8], wss[8];
    int wid = tid >> 5, lane = tid & 31;
    if (lane == 0) { ws[wid] = (double)s; wss[wid] = (double)ss; }
    __syncthreads();
    if (tid == 0) {
        double S = 0.0, SS = 0.0;
#pragma unroll
        for (int i = 0; i < 8; i++) { S += ws[i]; SS += wss[i]; }
        atomicAdd(&g_sum[n], S);
        atomicAdd(&g_sumsq[n], SS);
    }
}

// ---------------------------------------------------------------------------
// K1w: sum of |weight|  (for the TTQ threshold)
// ---------------------------------------------------------------------------
__global__ void k_wabs(const float* __restrict__ w) {
    int tid = threadIdx.x;
    float s = 0.f;
    for (int i = blockIdx.x * 256 + tid; i < WTOT; i += gridDim.x * 256)
        s += fabsf(w[i]);
#pragma unroll
    for (int off = 16; off; off >>= 1) s += __shfl_xor_sync(0xffffffffu, s, off);
    __shared__ double ws[8];
    int wid = tid >> 5, lane = tid & 31;
    if (lane == 0) ws[wid] = (double)s;
    __syncthreads();
    if (tid == 0) {
        double S = 0.0;
#pragma unroll
        for (int i = 0; i < 8; i++) S += ws[i];
        atomicAdd(&g_wabs, S);
    }
}

// ---------------------------------------------------------------------------
// per-sample mean / inv-std helper (identical math everywhere it is used)
// ---------------------------------------------------------------------------
__device__ __forceinline__ void sample_stats(int n, float& fm, float& istd) {
    double S = g_sum[n], SS = g_sumsq[n];
    double m = S * (1.0 / (double)NPIX);
    double v = SS * (1.0 / (double)NPIX) - m * m;
    fm = (float)m;
    istd = 1.0f / sqrtf((float)v + GN_EPSF);
}

// ---------------------------------------------------------------------------
// K2: global max |groupnorm(x)|   (uint-bits atomicMax; values are >= 0)
// same partition as k_stats
// ---------------------------------------------------------------------------
__global__ void k_max(const float* __restrict__ x,
                      const float* __restrict__ lnw,
                      const float* __restrict__ lnb) {
    int n = blockIdx.y;
    float fm, istd;
    sample_stats(n, fm, istd);
    const float* p = x + (size_t)n * NPIX + (size_t)blockIdx.x * 16384;
    int base = blockIdx.x * 16384;
    int tid = threadIdx.x;
    float m = 0.f;
#pragma unroll
    for (int k = 0; k < 16; k++) {
        int i = base + tid * 4 + k * 1024;       // elem idx within sample
        int c = i >> 12;                          // channel (4096 = H*W)
        float g = lnw[c], b = lnb[c];
        float4 v = *(const float4*)(p + tid * 4 + k * 1024);
        m = fmaxf(m, fabsf(((v.x - fm) * istd) * g + b));
        m = fmaxf(m, fabsf(((v.y - fm) * istd) * g + b));
        m = fmaxf(m, fabsf(((v.z - fm) * istd) * g + b));
        m = fmaxf(m, fabsf(((v.w - fm) * istd) * g + b));
    }
#pragma unroll
    for (int off = 16; off; off >>= 1) m = fmaxf(m, __shfl_xor_sync(0xffffffffu, m, off));
    __shared__ float wm[8];
    int wid = tid >> 5, lane = tid & 31;
    if (lane == 0) wm[wid] = m;
    __syncthreads();
    if (tid == 0) {
#pragma unroll
        for (int i = 1; i < 8; i++) m = fmaxf(m, wm[i]);
        atomicMax(&g_maxbits, __float_as_uint(m));
    }
}

// ---------------------------------------------------------------------------
// K2b: finalize scalars (tiny)
// ---------------------------------------------------------------------------
__global__ void k_post() {
    int t = threadIdx.x;
    if (t < Nn) {
        float fm, istd;
        sample_stats(t, fm, istd);
        g_meanf[t] = fm;
        g_istdf[t] = istd;
    }
    if (t == 0) {
        float gamma = fmaxf(__uint_as_float(g_maxbits), 1e-6f);
        g_qscale = 128.0f / gamma;
        g_coef = 0.01f * gamma * (1.0f / 128.0f);   // SCALE * gamma / Q_B
        g_delta = 0.7f * (float)(g_wabs * (1.0 / (double)WTOT));
    }
}

// ---------------------------------------------------------------------------
// K3: quantize activations into zero-padded scratch [n][c][66][72]
// interior rows/cols 1..64 hold data; everything else is 0 (conv halo)
// ---------------------------------------------------------------------------
__global__ void k_quant(const float* __restrict__ x,
                        const float* __restrict__ lnw,
                        const float* __restrict__ lnb) {
    int idx = blockIdx.x * 256 + threadIdx.x;     // PADTOT is a multiple of 256
    int n  = idx / (Cc * PH * PW);
    int r  = idx - n * (Cc * PH * PW);
    int c  = r / (PH * PW);
    int r2 = r - c * (PH * PW);
    int ph = r2 / PW;
    int pw = r2 - ph * PW;
    float q = 0.f;
    if ((unsigned)(ph - 1) < 64u && (unsigned)(pw - 1) < 64u) {
        float v = x[(((size_t)n * Cc + c) * Hh + (ph - 1)) * Ww + (pw - 1)];
        float xl = ((v - g_meanf[n]) * g_istdf[n]) * lnw[c] + lnb[c];
        float z = xl * g_qscale;
        z = fminf(fmaxf(z, -128.0f), 128.0f);     // fp32(±(128-1e-6)) == ±128.0f
        q = rintf(z);                             // round-half-even, matches jnp.round
    }
    g_xq[idx] = q;
}

// ---------------------------------------------------------------------------
// K3w: ternarize weights into [tap(9)][ic][oc] layout, values in {-1,0,+1}
// (the 0.01 scale is folded into the conv epilogue -> exact integer conv)
// ---------------------------------------------------------------------------
__global__ void k_wquant(const float* __restrict__ w) {
    int idx = blockIdx.x * 256 + threadIdx.x;     // WTOT multiple of 256
    int t   = idx >> 16;                          // / 65536
    int rem = idx & 65535;
    int ic  = rem >> 8;
    int oc  = rem & 255;
    int ky = t / 3, kx = t - ky * 3;
    float v = w[((oc * Cc + ic) * 3 + ky) * 3 + kx];
    float d = g_delta;
    g_wqT[idx] = (v > d) ? 1.0f : ((v < -d) ? -1.0f : 0.0f);
}

// ---------------------------------------------------------------------------
// K4: direct conv, GEMM-style tiling.
// Block: 64 oc x (4 rows x 64 cols) outputs, 256 threads, 8x8 per thread.
// Input staged per ic-chunk of 8 from padded scratch (no boundary branches).
// ---------------------------------------------------------------------------
#define ICC 8
#define SIN_RS 76                      // padded smem row stride (floats)

__global__ __launch_bounds__(256, 2)
void k_conv(const float* __restrict__ bias, float* __restrict__ out) {
    __shared__ __align__(16) float sIn[ICC * 6 * SIN_RS];   // 14592 B
    __shared__ __align__(16) float sW[9 * ICC * 64];        // 18432 B

    int b = blockIdx.x;
    int ocb = b & 3;
    int rt  = (b >> 2) & 15;
    int n   = b >> 6;
    int ocBase  = ocb * 64;
    int rowBase = rt * 4;          // padded row index of first needed input row

    int tid = threadIdx.x;
    int og  = tid >> 5;            // 0..7 : oc group (one per warp -> broadcast weights)
    int pg  = tid & 31;
    int ry2 = pg >> 4;             // 0..1 : row pair
    int cx  = pg & 15;             // 0..15: col quad

    float acc[8][8];
#pragma unroll
    for (int o = 0; o < 8; o++)
#pragma unroll
        for (int p = 0; p < 8; p++) acc[o][p] = 0.f;

    const float* gin = g_xq + (size_t)n * Cc * PH * PW;

    for (int ic0 = 0; ic0 < Cc; ic0 += ICC) {
        // stage input: ICC x 6 rows x 72 cols (float4), into stride-76 smem
        for (int i = tid; i < ICC * 6 * 18; i += 256) {
            int ic = i / 108;
            int rr = i - ic * 108;
            int rrow = rr / 18;
            int p4 = rr - rrow * 18;
            float4 v = *(const float4*)(gin + ((size_t)(ic0 + ic) * PH + rowBase + rrow) * PW + p4 * 4);
            *(float4*)&sIn[ic * (6 * SIN_RS) + rrow * SIN_RS + p4 * 4] = v;
        }
        // stage weights: 9 taps x ICC x 64 oc
        for (int i = tid; i < 9 * ICC * 16; i += 256) {
            int t  = i / (ICC * 16);
            int rr = i - t * (ICC * 16);
            int ic = rr >> 4;
            int o4 = rr & 15;
            float4 v = *(const float4*)(g_wqT + t * 65536 + (ic0 + ic) * 256 + ocBase + o4 * 4);
            *(float4*)&sW[(t * ICC + ic) * 64 + o4 * 4] = v;
        }
        __syncthreads();

        for (int ic = 0; ic < ICC; ic++) {
            // load 4 input rows x 6 cols for this thread's tile
            float a[4][6];
#pragma unroll
            for (int rr = 0; rr < 4; rr++) {
                const float* p = &sIn[ic * (6 * SIN_RS) + (2 * ry2 + rr) * SIN_RS + 4 * cx];
                float4 u = *(const float4*)p;
                float2 u2 = *(const float2*)(p + 4);
                a[rr][0] = u.x; a[rr][1] = u.y; a[rr][2] = u.z; a[rr][3] = u.w;
                a[rr][4] = u2.x; a[rr][5] = u2.y;
            }
#pragma unroll
            for (int ky = 0; ky < 3; ky++) {
#pragma unroll
                for (int kx = 0; kx < 3; kx++) {
                    const float* wp = &sW[((ky * 3 + kx) * ICC + ic) * 64 + og * 8];
                    float4 q0 = *(const float4*)wp;
                    float4 q1 = *(const float4*)(wp + 4);
                    float w[8] = {q0.x, q0.y, q0.z, q0.w, q1.x, q1.y, q1.z, q1.w};
#pragma unroll
                    for (int o = 0; o < 8; o++) {
#pragma unroll
                        for (int j = 0; j < 4; j++) {
                            acc[o][j]     += w[o] * a[ky][kx + j];
                            acc[o][4 + j] += w[o] * a[ky + 1][kx + j];
                        }
                    }
                }
            }
        }
        __syncthreads();
    }

    float coef = g_coef;
#pragma unroll
    for (int o = 0; o < 8; o++) {
        int oc = ocBase + og * 8 + o;
        float bz = bias[oc];
#pragma unroll
        for (int rr = 0; rr < 2; rr++) {
            int oh = rowBase + 2 * ry2 + rr;
            float4 v;
            v.x = acc[o][rr * 4 + 0] * coef + bz;
            v.y = acc[o][rr * 4 + 1] * coef + bz;
            v.z = acc[o][rr * 4 + 2] * coef + bz;
            v.w = acc[o][rr * 4 + 3] * coef + bz;
            *(float4*)(out + (((size_t)n * Cc + oc) * Hh + oh) * Ww + 4 * cx) = v;
        }
    }
}

// ---------------------------------------------------------------------------
// Launch
// ---------------------------------------------------------------------------
extern "C" void kernel_launch(void* const* d_in, const int* in_sizes, int n_in,
                              void* d_out, int out_size) {
    const float* x    = (const float*)d_in[0];
    const float* w    = (const float*)d_in[1];
    const float* bias = (const float*)d_in[2];
    const float* lnw  = (const float*)d_in[3];
    const float* lnb  = (const float*)d_in[4];
    float* out = (float*)d_out;

    k_init<<<1, 32>>>();
    k_stats<<<dim3(64, Nn), 256>>>(x);
    k_wabs<<<64, 256>>>(w);
    k_max<<<dim3(64, Nn), 256>>>(x, lnw, lnb);
    k_post<<<1, 32>>>();
    k_quant<<<PADTOT / 256, 256>>>(x, lnw, lnb);
    k_wquant<<<WTOT / 256, 256>>>(w);
    k_conv<<<1024, 256>>>(bias, out);
}

// round 4
// speedup vs baseline: 6.0578x; 6.0578x over previous
#include <cuda_runtime.h>
#include <cuda_bf16.h>
#include <math.h>
#include <stdint.h>

// ---------------------------------------------------------------------------
// Problem constants
// ---------------------------------------------------------------------------
#define Nn   16
#define Cc   256
#define Hh   64
#define Ww   64
#define PP   66                       // padded spatial (1 halo each side)
#define NPIX (Cc*Hh*Ww)               // per-sample elements (GroupNorm group)
#define XQTOT (Nn*PP*PP*Cc)           // NHWC padded bf16 activations
#define WTOT (Cc*Cc*9)
#define GN_EPSF 1e-5f

// ---------------------------------------------------------------------------
// Scratch (__device__ globals; no allocation anywhere)
// ---------------------------------------------------------------------------
__device__ __align__(1024) __nv_bfloat16 g_xq[XQTOT];   // [n][ph][pw][ic]
__device__ __align__(1024) __nv_bfloat16 g_wq[WTOT];    // [tap][ic][oc], {-1,0,1}
__device__ double g_sum[Nn];
__device__ double g_sumsq[Nn];
__device__ double g_wabs;
__device__ unsigned int g_maxbits;
__device__ float g_meanf[Nn], g_istdf[Nn];
__device__ float g_qscale;   // 128 / gamma
__device__ float g_coef;     // 0.01 * gamma / 128
__device__ float g_delta;    // 0.7 * mean|w|

// ---------------------------------------------------------------------------
// Portable PTX helpers (sm_80+ features only; compile under plain sm_100)
// ---------------------------------------------------------------------------
__device__ __forceinline__ uint32_t smem_u32(const void* p) {
    uint32_t a;
    asm("{ .reg .u64 t; cvta.to.shared.u64 t, %1; cvt.u32.u64 %0, t; }" : "=r"(a) : "l"(p));
    return a;
}
__device__ __forceinline__ void cp16(uint32_t dst, const void* src) {
    asm volatile("cp.async.cg.shared.global [%0], [%1], 16;" :: "r"(dst), "l"(src) : "memory");
}
__device__ __forceinline__ void cp_commit() {
    asm volatile("cp.async.commit_group;" ::: "memory");
}
__device__ __forceinline__ void ldsm_x4(uint32_t a, uint32_t& r0, uint32_t& r1,
                                        uint32_t& r2, uint32_t& r3) {
    asm volatile("ldmatrix.sync.aligned.m8n8.x4.shared.b16 {%0,%1,%2,%3}, [%4];"
                 : "=r"(r0), "=r"(r1), "=r"(r2), "=r"(r3) : "r"(a));
}
__device__ __forceinline__ void ldsm_x4t(uint32_t a, uint32_t& r0, uint32_t& r1,
                                         uint32_t& r2, uint32_t& r3) {
    asm volatile("ldmatrix.sync.aligned.m8n8.x4.trans.shared.b16 {%0,%1,%2,%3}, [%4];"
                 : "=r"(r0), "=r"(r1), "=r"(r2), "=r"(r3) : "r"(a));
}
__device__ __forceinline__ void mma16816(float* d, const uint32_t* a,
                                         uint32_t b0, uint32_t b1) {
    asm volatile(
        "mma.sync.aligned.m16n8k16.row.col.f32.bf16.bf16.f32 "
        "{%0,%1,%2,%3}, {%4,%5,%6,%7}, {%8,%9}, {%0,%1,%2,%3};"
        : "+f"(d[0]), "+f"(d[1]), "+f"(d[2]), "+f"(d[3])
        : "r"(a[0]), "r"(a[1]), "r"(a[2]), "r"(a[3]), "r"(b0), "r"(b1));
}

// ---------------------------------------------------------------------------
// K0: zero reduction scratch
// ---------------------------------------------------------------------------
__global__ void k_init() {
    int t = threadIdx.x;
    if (t < Nn) { g_sum[t] = 0.0; g_sumsq[t] = 0.0; }
    if (t == 0) { g_wabs = 0.0; g_maxbits = 0u; }
}

// ---------------------------------------------------------------------------
// K1: per-sample sum / sumsq
// ---------------------------------------------------------------------------
__global__ void k_stats(const float* __restrict__ x) {
    int n = blockIdx.y;
    const float* p = x + (size_t)n * NPIX + (size_t)blockIdx.x * 16384;
    int tid = threadIdx.x;
    float s = 0.f, ss = 0.f;
#pragma unroll
    for (int k = 0; k < 16; k++) {
        float4 v = *(const float4*)(p + tid * 4 + k * 1024);
        s  += v.x + v.y + v.z + v.w;
        ss += v.x*v.x + v.y*v.y + v.z*v.z + v.w*v.w;
    }
#pragma unroll
    for (int off = 16; off; off >>= 1) {
        s  += __shfl_xor_sync(0xffffffffu, s,  off);
        ss += __shfl_xor_sync(0xffffffffu, ss, off);
    }
    __shared__ double ws[8], wss[8];
    int wid = tid >> 5, lane = tid & 31;
    if (lane == 0) { ws[wid] = (double)s; wss[wid] = (double)ss; }
    __syncthreads();
    if (tid == 0) {
        double S = 0.0, SS = 0.0;
#pragma unroll
        for (int i = 0; i < 8; i++) { S += ws[i]; SS += wss[i]; }
        atomicAdd(&g_sum[n], S);
        atomicAdd(&g_sumsq[n], SS);
    }
}

// ---------------------------------------------------------------------------
// K1w: sum |w|
// ---------------------------------------------------------------------------
__global__ void k_wabs(const float* __restrict__ w) {
    int tid = threadIdx.x;
    float s = 0.f;
    for (int i = blockIdx.x * 256 + tid; i < WTOT; i += gridDim.x * 256)
        s += fabsf(w[i]);
#pragma unroll
    for (int off = 16; off; off >>= 1) s += __shfl_xor_sync(0xffffffffu, s, off);
    __shared__ double ws[8];
    int wid = tid >> 5, lane = tid & 31;
    if (lane == 0) ws[wid] = (double)s;
    __syncthreads();
    if (tid == 0) {
        double S = 0.0;
#pragma unroll
        for (int i = 0; i < 8; i++) S += ws[i];
        atomicAdd(&g_wabs, S);
    }
}

__device__ __forceinline__ void sample_stats(int n, float& fm, float& istd) {
    double S = g_sum[n], SS = g_sumsq[n];
    double m = S * (1.0 / (double)NPIX);
    double v = SS * (1.0 / (double)NPIX) - m * m;
    fm = (float)m;
    istd = 1.0f / sqrtf((float)v + GN_EPSF);
}

// ---------------------------------------------------------------------------
// K2: global max |groupnorm(x)|
// ---------------------------------------------------------------------------
__global__ void k_max(const float* __restrict__ x,
                      const float* __restrict__ lnw,
                      const float* __restrict__ lnb) {
    int n = blockIdx.y;
    float fm, istd;
    sample_stats(n, fm, istd);
    const float* p = x + (size_t)n * NPIX + (size_t)blockIdx.x * 16384;
    int base = blockIdx.x * 16384;
    int tid = threadIdx.x;
    float m = 0.f;
#pragma unroll
    for (int k = 0; k < 16; k++) {
        int i = base + tid * 4 + k * 1024;
        int c = i >> 12;
        float g = lnw[c], b = lnb[c];
        float4 v = *(const float4*)(p + tid * 4 + k * 1024);
        m = fmaxf(m, fabsf(((v.x - fm) * istd) * g + b));
        m = fmaxf(m, fabsf(((v.y - fm) * istd) * g + b));
        m = fmaxf(m, fabsf(((v.z - fm) * istd) * g + b));
        m = fmaxf(m, fabsf(((v.w - fm) * istd) * g + b));
    }
#pragma unroll
    for (int off = 16; off; off >>= 1) m = fmaxf(m, __shfl_xor_sync(0xffffffffu, m, off));
    __shared__ float wm[8];
    int wid = tid >> 5, lane = tid & 31;
    if (lane == 0) wm[wid] = m;
    __syncthreads();
    if (tid == 0) {
#pragma unroll
        for (int i = 1; i < 8; i++) m = fmaxf(m, wm[i]);
        atomicMax(&g_maxbits, __float_as_uint(m));
    }
}

// ---------------------------------------------------------------------------
// K2b: finalize scalars
// ---------------------------------------------------------------------------
__global__ void k_post() {
    int t = threadIdx.x;
    if (t < Nn) {
        float fm, istd;
        sample_stats(t, fm, istd);
        g_meanf[t] = fm;
        g_istdf[t] = istd;
    }
    if (t == 0) {
        float gamma = fmaxf(__uint_as_float(g_maxbits), 1e-6f);
        g_qscale = 128.0f / gamma;
        g_coef = 0.01f * gamma * (1.0f / 128.0f);
        g_delta = 0.7f * (float)(g_wabs * (1.0 / (double)WTOT));
    }
}

// ---------------------------------------------------------------------------
// K3a: zero the halo of g_xq (260 border pixels per sample, 512B each)
// ---------------------------------------------------------------------------
__global__ void k_halo() {
    int idx = blockIdx.x * 256 + threadIdx.x;       // 520 blocks
    int n = idx / (260 * 32);
    int r = idx - n * (260 * 32);
    int p = r >> 5, q = r & 31;
    int ph, pw;
    if (p < 66)       { ph = 0;       pw = p; }
    else if (p < 132) { ph = 65;      pw = p - 66; }
    else if (p < 196) { ph = p - 131; pw = 0; }
    else              { ph = p - 195; pw = 65; }
    uint4 z = make_uint4(0, 0, 0, 0);
    *(uint4*)(g_xq + ((size_t)(n * PP + ph) * PP + pw) * Cc + q * 8) = z;
}

// ---------------------------------------------------------------------------
// K3: quantize + NCHW->NHWC transpose into padded bf16 scratch
// ---------------------------------------------------------------------------
__global__ void k_quant_t(const float* __restrict__ x,
                          const float* __restrict__ lnw,
                          const float* __restrict__ lnb) {
    __shared__ float sm[64][68];
    int b = blockIdx.x;
    int ic4 = b & 3, h = (b >> 2) & 63, n = b >> 8;
    int tid = threadIdx.x;
    float mean = g_meanf[n], istd = g_istdf[n], qs = g_qscale;

    const float* xb = x + ((size_t)n * Cc + ic4 * 64) * 4096 + h * 64;
#pragma unroll
    for (int i = tid; i < 1024; i += 256) {
        int row = i >> 4, c4 = i & 15;
        float4 v = *(const float4*)(xb + (size_t)row * 4096 + c4 * 4);
        *(float4*)&sm[row][c4 * 4] = v;
    }
    __syncthreads();

    __nv_bfloat16* ob = g_xq + ((size_t)(n * PP + h + 1) * PP + 1) * Cc + ic4 * 64;
#pragma unroll
    for (int j = tid; j < 512; j += 256) {
        int p = j >> 3, seg = j & 7;
        unsigned short hv[8];
#pragma unroll
        for (int e = 0; e < 8; e++) {
            int cl = seg * 8 + e;
            int c = ic4 * 64 + cl;
            float v = sm[cl][p];
            float xl = ((v - mean) * istd) * lnw[c] + lnb[c];
            float z = fminf(fmaxf(xl * qs, -128.0f), 128.0f);
            hv[e] = __bfloat16_as_ushort(__float2bfloat16_rn(rintf(z)));
        }
        uint4 u;
        u.x = (uint32_t)hv[0] | ((uint32_t)hv[1] << 16);
        u.y = (uint32_t)hv[2] | ((uint32_t)hv[3] << 16);
        u.z = (uint32_t)hv[4] | ((uint32_t)hv[5] << 16);
        u.w = (uint32_t)hv[6] | ((uint32_t)hv[7] << 16);
        *(uint4*)(ob + (size_t)p * Cc + seg * 8) = u;
    }
}

// ---------------------------------------------------------------------------
// K3w: ternarize weights -> bf16 [tap][ic][oc]  ( = GEMM B, [k][n] row-major)
// ---------------------------------------------------------------------------
__global__ void k_wq(const float* __restrict__ w) {
    int idx = blockIdx.x * 256 + threadIdx.x;       // 2304 blocks
    int tap = idx >> 16;
    int rem = idx & 65535;
    int ic = rem >> 8, oc = rem & 255;
    float v = w[(size_t)(oc * Cc + ic) * 9 + tap];
    float d = g_delta;
    float q = (v > d) ? 1.f : ((v < -d) ? -1.f : 0.f);
    g_wq[idx] = __float2bfloat16_rn(q);
}

// ---------------------------------------------------------------------------
// K4: implicit-GEMM conv via mma.sync (portable sm_80+ path).
// CTA: 128 pixels (2 output rows) x 128 oc.  K = 9 taps x 256 ic, chunk 32.
// 4-stage cp.async ring; 8 warps in 2(M) x 4(N); warp tile 64px x 32oc.
// Epilogue: smem transpose -> float4 coalesced NCHW stores.
// ---------------------------------------------------------------------------
#define STAGES 4
#define STAGE_B 16384                 // 8KB A (128x32) + 8KB B (32x128)
#define CONV_SMEM (STAGES * STAGE_B)  // 64 KB, also reused by epilogue

__global__ void __launch_bounds__(256)
k_conv(const float* __restrict__ bias, float* __restrict__ out) {
    extern __shared__ __align__(1024) char smem[];
    uint32_t sb = smem_u32(smem);
    float* sbuf = (float*)smem;

    int tid = threadIdx.x, lid = tid & 31, wid = tid >> 5;
    int wm = wid & 1, wn = wid >> 1;              // warp grid 2(M) x 4(N)
    int b = blockIdx.x;
    int ocb = b & 1, rp = (b >> 1) & 31, n = b >> 6;
    int y0 = rp * 2, ocBase = ocb * 128;

    const __nv_bfloat16* xqn = g_xq + (size_t)n * PP * PP * Cc;

    // per-thread staging coordinates (invariant across chunks)
    int apx0 = tid >> 2, ac0 = tid & 3;           // A: t and t+256
    int apx1 = (tid + 256) >> 2, ac1 = tid & 3;
    int aph0 = ac0 ^ ((apx0 >> 1) & 3);
    int aph1 = ac1 ^ ((apx1 >> 1) & 3);
    int bk0 = tid >> 4, bc0 = tid & 15;
    int bk1 = (tid + 256) >> 4, bc1 = tid & 15;
    int bph0 = bc0 ^ (bk0 & 7);
    int bph1 = bc1 ^ (bk1 & 7);
    // A gmem pixel-part (row, col within padded plane), before tap shift
    int aRow0 = y0 + (apx0 >> 6), aCol0 = apx0 & 63;
    int aRow1 = y0 + (apx1 >> 6), aCol1 = apx1 & 63;

    float d[4][4][4];
#pragma unroll
    for (int i = 0; i < 4; i++)
#pragma unroll
        for (int j = 0; j < 4; j++)
#pragma unroll
            for (int e = 0; e < 4; e++) d[i][j][e] = 0.f;

    // ---- producer: stage chunk ch into ring slot s ----
    auto stage = [&](int ch, int s) {
        if (ch < 72) {
            int tap = ch >> 3, icc = ch & 7;
            int ic0 = icc * 32;
            int ky = (tap >= 6) ? 2 : ((tap >= 3) ? 1 : 0);
            int kx = tap - ky * 3;
            uint32_t As = sb + s * STAGE_B;
            uint32_t Bs = As + 8192;
            const __nv_bfloat16* srcA0 =
                xqn + ((size_t)(aRow0 + ky) * PP + aCol0 + kx) * Cc + ic0 + ac0 * 8;
            const __nv_bfloat16* srcA1 =
                xqn + ((size_t)(aRow1 + ky) * PP + aCol1 + kx) * Cc + ic0 + ac1 * 8;
            cp16(As + apx0 * 64 + aph0 * 16, srcA0);
            cp16(As + apx1 * 64 + aph1 * 16, srcA1);
            const __nv_bfloat16* srcB0 = g_wq + tap * 65536 + (ic0 + bk0) * 256 + ocBase + bc0 * 8;
            const __nv_bfloat16* srcB1 = g_wq + tap * 65536 + (ic0 + bk1) * 256 + ocBase + bc1 * 8;
            cp16(Bs + bk0 * 256 + bph0 * 16, srcB0);
            cp16(Bs + bk1 * 256 + bph1 * 16, srcB1);
        }
        cp_commit();
    };

    // prologue: stages 0..2
    stage(0, 0); stage(1, 1); stage(2, 2);

    for (int it = 0; it < 72; it++) {
        __syncthreads();                           // prior consumers done with slot
        stage(it + 3, (it + 3) & 3);
        asm volatile("cp.async.wait_group 3;" ::: "memory");
        __syncthreads();                           // chunk `it` visible to all

        uint32_t As = sb + (it & 3) * STAGE_B;
        uint32_t Bs = As + 8192;
#pragma unroll
        for (int g = 0; g < 2; g++) {
            uint32_t a[4][4];
#pragma unroll
            for (int i = 0; i < 4; i++) {
                int px = wm * 64 + i * 16 + (lid & 15);
                int kb = g * 2 + (lid >> 4);
                int ph = kb ^ ((px >> 1) & 3);
                ldsm_x4(As + px * 64 + ph * 16, a[i][0], a[i][1], a[i][2], a[i][3]);
            }
            uint32_t bf[2][4];
#pragma unroll
            for (int jj = 0; jj < 2; jj++) {
                int k = g * 16 + (lid & 15);
                int cb = wn * 4 + jj * 2 + (lid >> 4);
                int ph = cb ^ (k & 7);
                ldsm_x4t(Bs + k * 256 + ph * 16, bf[jj][0], bf[jj][1], bf[jj][2], bf[jj][3]);
            }
#pragma unroll
            for (int i = 0; i < 4; i++) {
#pragma unroll
                for (int jj = 0; jj < 2; jj++) {
                    mma16816(d[i][jj * 2], a[i], bf[jj][0], bf[jj][1]);
                    mma16816(d[i][jj * 2 + 1], a[i], bf[jj][2], bf[jj][3]);
                }
            }
        }
    }
    asm volatile("cp.async.wait_group 0;" ::: "memory");
    __syncthreads();                               // all consumption finished

    // ---- epilogue: per-warp smem transpose -> coalesced NCHW float4 stores ----
    int wb = wid * 2048;                           // 8KB float region per warp
    int q = lid >> 2, t2 = (lid & 3) * 2;
#pragma unroll
    for (int i = 0; i < 4; i++) {
#pragma unroll
        for (int j = 0; j < 4; j++) {
            int px = i * 16 + q;
            int oc = j * 8 + t2;
            sbuf[wb + oc * 64 + px]           = d[i][j][0];
            sbuf[wb + (oc + 1) * 64 + px]     = d[i][j][1];
            sbuf[wb + oc * 64 + px + 8]       = d[i][j][2];
            sbuf[wb + (oc + 1) * 64 + px + 8] = d[i][j][3];
        }
    }
    __syncwarp();
    float coef = g_coef;
    int y = y0 + wm;
#pragma unroll
    for (int itr = 0; itr < 16; itr++) {
        int ocl = itr * 2 + (lid >> 4);
        int x4 = (lid & 15) * 4;
        float4 v = *(float4*)&sbuf[wb + ocl * 64 + x4];
        int oc = ocBase + wn * 32 + ocl;
        float bz = bias[oc];
        v.x = v.x * coef + bz;
        v.y = v.y * coef + bz;
        v.z = v.z * coef + bz;
        v.w = v.w * coef + bz;
        *(float4*)(out + (((size_t)n * Cc + oc) * Hh + y) * Ww + x4) = v;
    }
}

// ---------------------------------------------------------------------------
// Host launch
// ---------------------------------------------------------------------------
extern "C" void kernel_launch(void* const* d_in, const int* in_sizes, int n_in,
                              void* d_out, int out_size) {
    const float* x    = (const float*)d_in[0];
    const float* w    = (const float*)d_in[1];
    const float* bias = (const float*)d_in[2];
    const float* lnw  = (const float*)d_in[3];
    const float* lnb  = (const float*)d_in[4];
    float* out = (float*)d_out;

    cudaFuncSetAttribute(k_conv, cudaFuncAttributeMaxDynamicSharedMemorySize, CONV_SMEM);

    k_init<<<1, 32>>>();
    k_stats<<<dim3(64, Nn), 256>>>(x);
    k_wabs<<<64, 256>>>(w);
    k_max<<<dim3(64, Nn), 256>>>(x, lnw, lnb);
    k_post<<<1, 32>>>();
    k_halo<<<520, 256>>>();
    k_quant_t<<<4096, 256>>>(x, lnw, lnb);
    k_wq<<<2304, 256>>>(w);
    k_conv<<<1024, 256, CONV_SMEM>>>(bias, out);
}